// round 11
// baseline (speedup 1.0000x reference)
#include <cuda_runtime.h>
#include <cuda_bf16.h>
#include <math_constants.h>

// ---------------------------------------------------------------------------
// GATv2 encoder: 3 layers, N=50000 nodes, E=800000 edges.
//   1) CSR by dst (histogram + single-block scan + scatter).
//   2) Per layer: SGEMM (128x64x16 + register prefetch), then fused
//      warp-per-node PAIR-UNROLLED gather + packed-f32x2 score/aggregate +
//      merged online softmax (+ ELU).
//      lrelu(x) == 0.6x + 0.4|x|  =>  dot(a,lrelu(s)) = .6 dot(a,s) + .4 dot(a,|s|)
//   3) Coalesced atomic max pool -> d_out[64].
// ---------------------------------------------------------------------------

#define N_NODES 50000
#define E_EDGES 800000
#define NEG_SLOPE 0.2f

typedef unsigned long long u64;

__device__ float g_h[N_NODES * 256];
__device__ float g_feat[N_NODES * 256];
__device__ int   g_cnt[N_NODES];
__device__ int   g_roff[N_NODES + 1];
__device__ int   g_cur[N_NODES];
__device__ int   g_srcs[E_EDGES];
__device__ unsigned g_pool[64];

// ---------------- packed f32x2 helpers (Blackwell) -------------------------
__device__ __forceinline__ u64 pack2(float x, float y) {
    u64 r; asm("mov.b64 %0, {%1, %2};" : "=l"(r) : "f"(x), "f"(y)); return r;
}
__device__ __forceinline__ float2 unpack2(u64 v) {
    float2 f; asm("mov.b64 {%0, %1}, %2;" : "=f"(f.x), "=f"(f.y) : "l"(v)); return f;
}
__device__ __forceinline__ u64 addx2(u64 a, u64 b) {
    u64 r; asm("add.rn.f32x2 %0, %1, %2;" : "=l"(r) : "l"(a), "l"(b)); return r;
}
__device__ __forceinline__ u64 mulx2(u64 a, u64 b) {
    u64 r; asm("mul.rn.f32x2 %0, %1, %2;" : "=l"(r) : "l"(a), "l"(b)); return r;
}
__device__ __forceinline__ u64 fmax2(u64 a, u64 b, u64 c) {  // fma: a*b + c (packed)
    u64 r; asm("fma.rn.f32x2 %0, %1, %2, %3;" : "=l"(r) : "l"(a), "l"(b), "l"(c)); return r;
}
__device__ __forceinline__ u64 absx2(u64 a) { return a & 0x7FFFFFFF7FFFFFFFULL; }

// ---------------------------------------------------------------------------
// CSR build
// ---------------------------------------------------------------------------
__global__ void hist_kernel(const int* __restrict__ dst) {
    int e = blockIdx.x * blockDim.x + threadIdx.x;
    if (e < E_EDGES) atomicAdd(&g_cnt[dst[e]], 1);
}

__global__ void scan_kernel() {
    __shared__ int sh[1024];
    int t = threadIdx.x;
    const int per = (N_NODES + 1023) >> 10;  // 49
    int lo = t * per;
    int hi = lo + per; if (hi > N_NODES) hi = N_NODES;
    if (lo > N_NODES) lo = N_NODES;
    int sum = 0;
    for (int i = lo; i < hi; ++i) sum += g_cnt[i];
    sh[t] = sum;
    __syncthreads();
    for (int ofs = 1; ofs < 1024; ofs <<= 1) {
        int v = (t >= ofs) ? sh[t - ofs] : 0;
        __syncthreads();
        sh[t] += v;
        __syncthreads();
    }
    int run = (t == 0) ? 0 : sh[t - 1];
    for (int i = lo; i < hi; ++i) {
        g_roff[i] = run;
        g_cur[i]  = run;
        run += g_cnt[i];
    }
    if (t == 0) g_roff[N_NODES] = E_EDGES;
}

__global__ void scatter_kernel(const int* __restrict__ src, const int* __restrict__ dst) {
    int e = blockIdx.x * blockDim.x + threadIdx.x;
    if (e < E_EDGES) {
        int p = atomicAdd(&g_cur[dst[e]], 1);
        g_srcs[p] = src[e];
    }
}

// ---------------------------------------------------------------------------
// SGEMM 128x64x16, 256 threads, 8x4/thread, register-staged global prefetch.
// ---------------------------------------------------------------------------
__global__ __launch_bounds__(256) void sgemm_kernel(
    const float* __restrict__ A, const float* __restrict__ W,
    const float* __restrict__ bias, float* __restrict__ C,
    int M, int K, int Ncol)
{
    __shared__ float As[16][128 + 4];
    __shared__ float Bs[16][64];
    const int tid = threadIdx.x;
    const int br = blockIdx.x * 128;
    const int bc = blockIdx.y * 64;
    const int ty = tid >> 4;
    const int tx = tid & 15;

    float acc[8][4];
#pragma unroll
    for (int i = 0; i < 8; ++i)
#pragma unroll
        for (int j = 0; j < 4; ++j) acc[i][j] = 0.f;

    const int a_r0 = tid >> 2;
    const int a_c  = (tid & 3) << 2;
    const int b_r  = tid >> 4;
    const int b_c  = (tid & 15) << 2;

    const bool av0 = (br + a_r0) < M;
    const bool av1 = (br + a_r0 + 64) < M;
    const float* Ap0 = A + (size_t)(br + a_r0) * K + a_c;
    const float* Ap1 = A + (size_t)(br + a_r0 + 64) * K + a_c;
    const float* Wp  = W + (size_t)b_r * Ncol + bc + b_c;

    const float4 z4 = make_float4(0.f, 0.f, 0.f, 0.f);
    float4 va0 = av0 ? *(const float4*)Ap0 : z4;
    float4 va1 = av1 ? *(const float4*)Ap1 : z4;
    float4 vb  = *(const float4*)Wp;

    const int nT = K >> 4;
    for (int t = 0; t < nT; ++t) {
        As[a_c + 0][a_r0] = va0.x;
        As[a_c + 1][a_r0] = va0.y;
        As[a_c + 2][a_r0] = va0.z;
        As[a_c + 3][a_r0] = va0.w;
        As[a_c + 0][a_r0 + 64] = va1.x;
        As[a_c + 1][a_r0 + 64] = va1.y;
        As[a_c + 2][a_r0 + 64] = va1.z;
        As[a_c + 3][a_r0 + 64] = va1.w;
        *(float4*)&Bs[b_r][b_c] = vb;
        __syncthreads();

        if (t + 1 < nT) {
            va0 = av0 ? *(const float4*)(Ap0 + (t + 1) * 16) : z4;
            va1 = av1 ? *(const float4*)(Ap1 + (t + 1) * 16) : z4;
            vb  = *(const float4*)(Wp + (size_t)(t + 1) * 16 * Ncol);
        }
#pragma unroll
        for (int k = 0; k < 16; ++k) {
            float4 b4  = *(const float4*)&Bs[k][tx << 2];
            float4 alo = *(const float4*)&As[k][ty << 3];
            float4 ahi = *(const float4*)&As[k][(ty << 3) + 4];
            float av[8] = {alo.x, alo.y, alo.z, alo.w, ahi.x, ahi.y, ahi.z, ahi.w};
            float bv[4] = {b4.x, b4.y, b4.z, b4.w};
#pragma unroll
            for (int i = 0; i < 8; ++i)
#pragma unroll
                for (int j = 0; j < 4; ++j)
                    acc[i][j] = fmaf(av[i], bv[j], acc[i][j]);
        }
        __syncthreads();
    }

    float4 bb = *(const float4*)(bias + bc + (tx << 2));
    float bv[4] = {bb.x, bb.y, bb.z, bb.w};
#pragma unroll
    for (int i = 0; i < 8; ++i) {
        int gr = br + (ty << 3) + i;
        if (gr < M) {
            float4 o;
            o.x = acc[i][0] + bv[0];
            o.y = acc[i][1] + bv[1];
            o.z = acc[i][2] + bv[2];
            o.w = acc[i][3] + bv[3];
            *(float4*)(C + (size_t)gr * Ncol + bc + (tx << 2)) = o;
        }
    }
}

// ---------------------------------------------------------------------------
// Fused GAT edge kernels, packed-f32x2 arithmetic.
// ---------------------------------------------------------------------------
__device__ __forceinline__ float elu1(float x) { return x > 0.f ? x : (__expf(x) - 1.f); }

// score contribution of ONE 4-float chunk (one ulonglong2) vs dest:
//   s = hs + hd; d1 = a.s; d2 = a.|s|; part = 0.6*d1 + 0.4*d2
__device__ __forceinline__ float score4(
    ulonglong2 hs, ulonglong2 hd, ulonglong2 a, u64 C06, u64 C04)
{
    u64 s0 = addx2(hs.x, hd.x);
    u64 s1 = addx2(hs.y, hd.y);
    u64 d1 = fmax2(a.x, s0, mulx2(a.y, s1));
    u64 d2 = fmax2(a.x, absx2(s0), mulx2(a.y, absx2(s1)));
    u64 cb = fmax2(C06, d1, mulx2(C04, d2));
    float2 t = unpack2(cb);
    return t.x + t.y;
}

__global__ __launch_bounds__(128) void gat_edge_h8(
    const float* __restrict__ h, const float* __restrict__ attnw,
    float* __restrict__ outp, int applyElu)
{
    int warp = (blockIdx.x * blockDim.x + threadIdx.x) >> 5;
    int lane = threadIdx.x & 31;
    if (warp >= N_NODES) return;
    const int n = warp;
    const ulonglong2* __restrict__ h4 = (const ulonglong2*)h;
    const ulonglong2* __restrict__ a4 = (const ulonglong2*)attnw;

    const u64 C06 = pack2(0.6f, 0.6f);
    const u64 C04 = pack2(0.4f, 0.4f);

    ulonglong2 a0 = a4[lane];
    ulonglong2 a1 = a4[32 + lane];
    ulonglong2 hd0 = h4[(size_t)n * 64 + lane];
    ulonglong2 hd1 = h4[(size_t)n * 64 + 32 + lane];

    float m0 = -CUDART_INF_F, m1 = -CUDART_INF_F;
    float s0 = 0.f, s1 = 0.f;
    u64 acc00 = 0ULL, acc01 = 0ULL, acc10 = 0ULL, acc11 = 0ULL;

    const int beg = g_roff[n], end = g_roff[n + 1];
    int iA = g_srcs[beg];                           // degree >= 1 (self-edge)
    int iB = (beg + 1 < end) ? g_srcs[beg + 1] : iA;
    ulonglong2 A0 = h4[(size_t)iA * 64 + lane];
    ulonglong2 A1 = h4[(size_t)iA * 64 + 32 + lane];
    ulonglong2 B0 = h4[(size_t)iB * 64 + lane];
    ulonglong2 B1 = h4[(size_t)iB * 64 + 32 + lane];

    int j = beg;
    for (; j + 1 < end; j += 2) {
        int jn = j + 2;
        int nAi = (jn < end) ? g_srcs[jn] : 0;
        int nBi = (jn + 1 < end) ? g_srcs[jn + 1] : nAi;
        ulonglong2 nA0 = h4[(size_t)nAi * 64 + lane];
        ulonglong2 nA1 = h4[(size_t)nAi * 64 + 32 + lane];
        ulonglong2 nB0 = h4[(size_t)nBi * 64 + lane];
        ulonglong2 nB1 = h4[(size_t)nBi * 64 + 32 + lane];

        // p-side: (row half 0, a0, hd0); q-side: (half 1, a1, hd1)
        float pA = score4(A0, hd0, a0, C06, C04);
        float qA = score4(A1, hd1, a1, C06, C04);
        float pB = score4(B0, hd0, a0, C06, C04);
        float qB = score4(B1, hd1, a1, C06, C04);

        pA += __shfl_xor_sync(0xFFFFFFFFu, pA, 1);
        pB += __shfl_xor_sync(0xFFFFFFFFu, pB, 1);
        qA += __shfl_xor_sync(0xFFFFFFFFu, qA, 1);
        qB += __shfl_xor_sync(0xFFFFFFFFu, qB, 1);
        pA += __shfl_xor_sync(0xFFFFFFFFu, pA, 2);
        pB += __shfl_xor_sync(0xFFFFFFFFu, pB, 2);
        qA += __shfl_xor_sync(0xFFFFFFFFu, qA, 2);
        qB += __shfl_xor_sync(0xFFFFFFFFu, qB, 2);
        pA += __shfl_xor_sync(0xFFFFFFFFu, pA, 4);
        pB += __shfl_xor_sync(0xFFFFFFFFu, pB, 4);
        qA += __shfl_xor_sync(0xFFFFFFFFu, qA, 4);
        qB += __shfl_xor_sync(0xFFFFFFFFu, qB, 4);

        {
            float nm = fmaxf(m0, fmaxf(pA, pB));
            float c  = __expf(m0 - nm);
            float eA = __expf(pA - nm);
            float eB = __expf(pB - nm);
            s0 = fmaf(s0, c, eA + eB); m0 = nm;
            u64 cp = pack2(c, c), eAp = pack2(eA, eA), eBp = pack2(eB, eB);
            acc00 = fmax2(eBp, B0.x, fmax2(eAp, A0.x, mulx2(cp, acc00)));
            acc01 = fmax2(eBp, B0.y, fmax2(eAp, A0.y, mulx2(cp, acc01)));
        }
        {
            float nm = fmaxf(m1, fmaxf(qA, qB));
            float c  = __expf(m1 - nm);
            float eA = __expf(qA - nm);
            float eB = __expf(qB - nm);
            s1 = fmaf(s1, c, eA + eB); m1 = nm;
            u64 cp = pack2(c, c), eAp = pack2(eA, eA), eBp = pack2(eB, eB);
            acc10 = fmax2(eBp, B1.x, fmax2(eAp, A1.x, mulx2(cp, acc10)));
            acc11 = fmax2(eBp, B1.y, fmax2(eAp, A1.y, mulx2(cp, acc11)));
        }
        A0 = nA0; A1 = nA1; B0 = nB0; B1 = nB1;
    }

    if (j < end) {  // odd tail; rows already in A0/A1
        float p = score4(A0, hd0, a0, C06, C04);
        float q = score4(A1, hd1, a1, C06, C04);
        p += __shfl_xor_sync(0xFFFFFFFFu, p, 1);
        q += __shfl_xor_sync(0xFFFFFFFFu, q, 1);
        p += __shfl_xor_sync(0xFFFFFFFFu, p, 2);
        q += __shfl_xor_sync(0xFFFFFFFFu, q, 2);
        p += __shfl_xor_sync(0xFFFFFFFFu, p, 4);
        q += __shfl_xor_sync(0xFFFFFFFFu, q, 4);

        float nm = fmaxf(m0, p);
        float c  = __expf(m0 - nm);
        float e  = __expf(p - nm);
        s0 = fmaf(s0, c, e); m0 = nm;
        u64 cp = pack2(c, c), ep = pack2(e, e);
        acc00 = fmax2(ep, A0.x, mulx2(cp, acc00));
        acc01 = fmax2(ep, A0.y, mulx2(cp, acc01));

        nm = fmaxf(m1, q);
        c  = __expf(m1 - nm);
        e  = __expf(q - nm);
        s1 = fmaf(s1, c, e); m1 = nm;
        cp = pack2(c, c); ep = pack2(e, e);
        acc10 = fmax2(ep, A1.x, mulx2(cp, acc10));
        acc11 = fmax2(ep, A1.y, mulx2(cp, acc11));
    }

    float inv0 = (s0 > 0.f) ? (1.f / s0) : 0.f;
    float inv1 = (s1 > 0.f) ? (1.f / s1) : 0.f;
    u64 i0p = pack2(inv0, inv0), i1p = pack2(inv1, inv1);
    float2 r00 = unpack2(mulx2(acc00, i0p));
    float2 r01 = unpack2(mulx2(acc01, i0p));
    float2 r10 = unpack2(mulx2(acc10, i1p));
    float2 r11 = unpack2(mulx2(acc11, i1p));
    float4 o0 = make_float4(r00.x, r00.y, r01.x, r01.y);
    float4 o1 = make_float4(r10.x, r10.y, r11.x, r11.y);
    if (applyElu) {
        o0.x = elu1(o0.x); o0.y = elu1(o0.y); o0.z = elu1(o0.z); o0.w = elu1(o0.w);
        o1.x = elu1(o1.x); o1.y = elu1(o1.y); o1.z = elu1(o1.z); o1.w = elu1(o1.w);
    }
    float4* __restrict__ out4 = (float4*)outp;
    out4[(size_t)n * 64 + lane]      = o0;
    out4[(size_t)n * 64 + 32 + lane] = o1;
}

__global__ __launch_bounds__(256) void gat_edge_h1(
    const float* __restrict__ h, const float* __restrict__ attnw,
    float* __restrict__ outp)
{
    int warp = (blockIdx.x * blockDim.x + threadIdx.x) >> 5;
    int lane = threadIdx.x & 31;
    if (warp >= N_NODES) return;
    const int n = warp;
    const u64* __restrict__ h2 = (const u64*)h;
    const u64 C06 = pack2(0.6f, 0.6f);
    const u64 C04 = pack2(0.4f, 0.4f);
    u64 a  = ((const u64*)attnw)[lane];
    u64 hd = h2[(size_t)n * 32 + lane];

    float m = -CUDART_INF_F, ssum = 0.f;
    u64 acc = 0ULL;

    const int beg = g_roff[n], end = g_roff[n + 1];
    int iA = g_srcs[beg];
    int iB = (beg + 1 < end) ? g_srcs[beg + 1] : iA;
    u64 A = h2[(size_t)iA * 32 + lane];
    u64 B = h2[(size_t)iB * 32 + lane];

    int j = beg;
    for (; j + 1 < end; j += 2) {
        int jn = j + 2;
        int nAi = (jn < end) ? g_srcs[jn] : 0;
        int nBi = (jn + 1 < end) ? g_srcs[jn + 1] : nAi;
        u64 nA = h2[(size_t)nAi * 32 + lane];
        u64 nB = h2[(size_t)nBi * 32 + lane];

        u64 sA = addx2(A, hd);
        u64 sB = addx2(B, hd);
        u64 cA = fmax2(C06, mulx2(a, sA), mulx2(C04, mulx2(a, absx2(sA))));
        u64 cB = fmax2(C06, mulx2(a, sB), mulx2(C04, mulx2(a, absx2(sB))));
        float2 tA = unpack2(cA), tB = unpack2(cB);
        float pA = tA.x + tA.y, pB = tB.x + tB.y;
#pragma unroll
        for (int ofs = 1; ofs < 32; ofs <<= 1) {
            pA += __shfl_xor_sync(0xFFFFFFFFu, pA, ofs);
            pB += __shfl_xor_sync(0xFFFFFFFFu, pB, ofs);
        }

        float nm = fmaxf(m, fmaxf(pA, pB));
        float c  = __expf(m - nm);
        float eA = __expf(pA - nm);
        float eB = __expf(pB - nm);
        ssum = fmaf(ssum, c, eA + eB); m = nm;
        u64 cp = pack2(c, c), eAp = pack2(eA, eA), eBp = pack2(eB, eB);
        acc = fmax2(eBp, B, fmax2(eAp, A, mulx2(cp, acc)));

        A = nA; B = nB;
    }
    if (j < end) {
        u64 sA = addx2(A, hd);
        u64 cA = fmax2(C06, mulx2(a, sA), mulx2(C04, mulx2(a, absx2(sA))));
        float2 tA = unpack2(cA);
        float p = tA.x + tA.y;
#pragma unroll
        for (int ofs = 1; ofs < 32; ofs <<= 1)
            p += __shfl_xor_sync(0xFFFFFFFFu, p, ofs);
        float nm = fmaxf(m, p);
        float c  = __expf(m - nm);
        float e  = __expf(p - nm);
        ssum = fmaf(ssum, c, e); m = nm;
        u64 cp = pack2(c, c), ep = pack2(e, e);
        acc = fmax2(ep, A, mulx2(cp, acc));
    }
    float inv = (ssum > 0.f) ? (1.f / ssum) : 0.f;
    float2 o = unpack2(mulx2(acc, pack2(inv, inv)));
    ((float2*)outp)[(size_t)n * 32 + lane] = o;
}

// ---------------------------------------------------------------------------
// Coalesced max pool
// ---------------------------------------------------------------------------
__device__ __forceinline__ unsigned fmap(float f) {
    unsigned u = __float_as_uint(f);
    return (u & 0x80000000u) ? ~u : (u | 0x80000000u);
}

__global__ __launch_bounds__(256) void maxpool_kernel(const float* __restrict__ f) {
    __shared__ float4 sh[256];
    const float4* __restrict__ f4 = (const float4*)f;
    int cg = threadIdx.x & 15;
    int rr = threadIdx.x >> 4;
    float4 mx = make_float4(-CUDART_INF_F, -CUDART_INF_F, -CUDART_INF_F, -CUDART_INF_F);
    for (int n = blockIdx.x * 16 + rr; n < N_NODES; n += gridDim.x * 16) {
        float4 v = f4[(size_t)n * 16 + cg];
        mx.x = fmaxf(mx.x, v.x); mx.y = fmaxf(mx.y, v.y);
        mx.z = fmaxf(mx.z, v.z); mx.w = fmaxf(mx.w, v.w);
    }
    sh[threadIdx.x] = mx;
    __syncthreads();
    for (int ofs = 128; ofs >= 16; ofs >>= 1) {
        if (threadIdx.x < ofs) {
            float4 o = sh[threadIdx.x + ofs];
            float4 m2 = sh[threadIdx.x];
            m2.x = fmaxf(m2.x, o.x); m2.y = fmaxf(m2.y, o.y);
            m2.z = fmaxf(m2.z, o.z); m2.w = fmaxf(m2.w, o.w);
            sh[threadIdx.x] = m2;
        }
        __syncthreads();
    }
    if (threadIdx.x < 16) {
        float4 m2 = sh[threadIdx.x];
        atomicMax(&g_pool[threadIdx.x * 4 + 0], fmap(m2.x));
        atomicMax(&g_pool[threadIdx.x * 4 + 1], fmap(m2.y));
        atomicMax(&g_pool[threadIdx.x * 4 + 2], fmap(m2.z));
        atomicMax(&g_pool[threadIdx.x * 4 + 3], fmap(m2.w));
    }
}

__global__ void pool_final(float* __restrict__ out) {
    int c = threadIdx.x;
    if (c < 64) {
        unsigned v = g_pool[c];
        out[c] = (v & 0x80000000u) ? __uint_as_float(v ^ 0x80000000u)
                                   : __uint_as_float(~v);
    }
}

// ---------------------------------------------------------------------------
// Launch
// ---------------------------------------------------------------------------
extern "C" void kernel_launch(void* const* d_in, const int* in_sizes, int n_in,
                              void* d_out, int out_size)
{
    const float* x   = (const float*)d_in[0];
    const int*   src = (const int*)d_in[1];
    const int*   dst = (const int*)d_in[2];
    const float* W1  = (const float*)d_in[3];
    const float* b1  = (const float*)d_in[4];
    const float* at1 = (const float*)d_in[5];
    const float* W2  = (const float*)d_in[6];
    const float* b2  = (const float*)d_in[7];
    const float* at2 = (const float*)d_in[8];
    const float* W3  = (const float*)d_in[9];
    const float* b3  = (const float*)d_in[10];
    const float* at3 = (const float*)d_in[11];
    float* out = (float*)d_out;

    float *hP = nullptr, *fP = nullptr;
    int *cntP = nullptr;
    unsigned* poolP = nullptr;
    cudaGetSymbolAddress((void**)&hP, g_h);
    cudaGetSymbolAddress((void**)&fP, g_feat);
    cudaGetSymbolAddress((void**)&cntP, g_cnt);
    cudaGetSymbolAddress((void**)&poolP, g_pool);

    cudaMemsetAsync(cntP, 0, N_NODES * sizeof(int));
    cudaMemsetAsync(poolP, 0, 64 * sizeof(unsigned));
    hist_kernel<<<(E_EDGES + 255) / 256, 256>>>(dst);
    scan_kernel<<<1, 1024>>>();
    scatter_kernel<<<(E_EDGES + 255) / 256, 256>>>(src, dst);

    const int grid_h8 = N_NODES / 4;   // 4 warps/block @128 threads
    const int grid_h1 = N_NODES / 8;   // 8 warps/block @256 threads

    // Layer 1: x[50000,128] @ W1[128,256]
    {
        dim3 g((N_NODES + 127) / 128, 256 / 64);
        sgemm_kernel<<<g, 256>>>(x, W1, b1, hP, N_NODES, 128, 256);
        gat_edge_h8<<<grid_h8, 128>>>(hP, at1, fP, 1);
    }
    // Layer 2: feat[50000,256] @ W2[256,256]
    {
        dim3 g((N_NODES + 127) / 128, 256 / 64);
        sgemm_kernel<<<g, 256>>>(fP, W2, b2, hP, N_NODES, 256, 256);
        gat_edge_h8<<<grid_h8, 128>>>(hP, at2, fP, 1);
    }
    // Layer 3: feat[50000,256] @ W3[256,64]
    {
        dim3 g((N_NODES + 127) / 128, 1);
        sgemm_kernel<<<g, 256>>>(fP, W3, b3, hP, N_NODES, 256, 64);
        gat_edge_h1<<<grid_h1, 256>>>(hP, at3, fP);
    }
    maxpool_kernel<<<196, 256>>>(fP);
    pool_final<<<1, 64>>>(out);
}